// round 16
// baseline (speedup 1.0000x reference)
#include <cuda_runtime.h>
#include <cstdint>

// Problem: input [B=128, C=2, H=512, W=512] fp32.
// out[:,0] = inclusive cumsum along x (contiguous axis)
// out[:,1] = inclusive cumsum along y (stride-W axis)
//
// One fused kernel, 512 threads/block, register-resident scans both roles:
//  x-role (4096 blocks): one warp per row; each lane owns 16 CONSECUTIVE
//    elements (4 float4s loaded upfront -> MLP=4), register-local scan,
//    then a single 5-step shfl_up warp scan. (R14's per-iteration
//    load->scan->store loop had MLP=1 and 24 shuffles/row.)
//  y-role (2048 blocks): 512x32 column tile, register-resident (R14 path):
//    8 consecutive rows of float4 per thread, stride-8/16 shfl combine,
//    2KB smem spine, one __syncthreads.
// Interleaved bid%3==0 -> y so both traffic types share every wave.

#define Wn 512
#define YCOLS 32                    // columns per y-block
#define Y_BLOCKS 2048               // 128 images * (512/32) col-tiles
#define X_BLOCKS 4096               // 65536 rows / 16 warps
#define GRID_BLOCKS (Y_BLOCKS + X_BLOCKS)
#define NTHREADS 512

__device__ __forceinline__ float4 shfl_up4(float4 v, int delta) {
    float4 r;
    r.x = __shfl_up_sync(0xffffffffu, v.x, delta);
    r.y = __shfl_up_sync(0xffffffffu, v.y, delta);
    r.z = __shfl_up_sync(0xffffffffu, v.z, delta);
    r.w = __shfl_up_sync(0xffffffffu, v.w, delta);
    return r;
}

__device__ __forceinline__ float4 shfl_idx4(float4 v, int src) {
    float4 r;
    r.x = __shfl_sync(0xffffffffu, v.x, src);
    r.y = __shfl_sync(0xffffffffu, v.y, src);
    r.z = __shfl_sync(0xffffffffu, v.z, src);
    r.w = __shfl_sync(0xffffffffu, v.w, src);
    return r;
}

// ---------------------------------------------------------------------------
// x-role: one warp per row of channel 0 (16 warps per block).
// Lane owns elements [lane*16, lane*16+16). All 4 loads issued upfront.
// ---------------------------------------------------------------------------
__device__ __forceinline__ void do_scan_x(const float* __restrict__ in,
                                          float* __restrict__ out,
                                          unsigned xbid) {
    const unsigned gwarp = xbid * 16u + (threadIdx.x >> 5);  // 0..65535
    const unsigned lane  = threadIdx.x & 31u;

    const unsigned b = gwarp >> 9;
    const unsigned y = gwarp & 511u;

    const size_t base = ((size_t)(b * 2u + 0u) * Wn + y) * Wn;  // channel 0
    const float4* __restrict__ in4  = (const float4*)(in + base);
    float4* __restrict__       out4 = (float4*)(out + base);

    // 4 independent loads (MLP=4, 2KB/warp in flight)
    float4 v[4];
#pragma unroll
    for (int j = 0; j < 4; ++j)
        v[j] = in4[lane * 4u + j];

    // register-local inclusive scan of the 16 elements
    v[0].y += v[0].x; v[0].z += v[0].y; v[0].w += v[0].z;
#pragma unroll
    for (int j = 1; j < 4; ++j) {
        v[j].x += v[j - 1].w;
        v[j].y += v[j].x;
        v[j].z += v[j].y;
        v[j].w += v[j].z;
    }

    // single warp scan over lane totals
    const float tot = v[3].w;
    float incl = tot;
#pragma unroll
    for (int off = 1; off < 32; off <<= 1) {
        float n = __shfl_up_sync(0xffffffffu, incl, off);
        if (lane >= (unsigned)off) incl += n;
    }
    const float excl = incl - tot;

#pragma unroll
    for (int j = 0; j < 4; ++j) {
        float4 o;
        o.x = v[j].x + excl;
        o.y = v[j].y + excl;
        o.z = v[j].z + excl;
        o.w = v[j].w + excl;
        out4[lane * 4u + j] = o;
    }
}

// ---------------------------------------------------------------------------
// y-role: 512x32 column tile of channel 1, register-resident scan.
// ---------------------------------------------------------------------------
__device__ __forceinline__ void do_scan_y(const float* __restrict__ in,
                                          float* __restrict__ out,
                                          unsigned ybid,
                                          float4* __restrict__ wtot) {
    const unsigned tid  = threadIdx.x;
    const unsigned quad = tid & 7u;            // float4 column group (0..7)
    const unsigned r    = tid >> 3;            // row-chunk (0..63)
    const unsigned w    = tid >> 5;            // warp (0..15)
    const unsigned lane = tid & 31u;
    const unsigned rloc = lane >> 3;           // row-chunk within warp (0..3)

    const unsigned b  = ybid >> 4;             // image (16 col-tiles/image)
    const unsigned tc = ybid & 15u;            // col-tile
    const size_t base = ((size_t)(b * 2u + 1u) * Wn) * Wn + tc * YCOLS;

    const float4* __restrict__ in4 = (const float4*)(in + base);
    float4* __restrict__ out4      = (float4*)(out + base);

    // ---- load 8 consecutive rows (float4 each) + local inclusive scan ----
    float4 v[8];
    const unsigned row0 = r * 8u;
#pragma unroll
    for (int j = 0; j < 8; ++j)
        v[j] = in4[(size_t)(row0 + j) * (Wn / 4) + quad];
#pragma unroll
    for (int j = 1; j < 8; ++j) {
        v[j].x += v[j - 1].x;
        v[j].y += v[j - 1].y;
        v[j].z += v[j - 1].z;
        v[j].w += v[j - 1].w;
    }

    // ---- warp scan over the 4 row-chunks (stride 8 lanes per chunk) ----
    float4 incl = v[7];
    {
        float4 n = shfl_up4(incl, 8);
        if (rloc >= 1) { incl.x += n.x; incl.y += n.y; incl.z += n.z; incl.w += n.w; }
        n = shfl_up4(incl, 16);
        if (rloc >= 2) { incl.x += n.x; incl.y += n.y; incl.z += n.z; incl.w += n.w; }
    }
    float4 wexcl;
    wexcl.x = incl.x - v[7].x;
    wexcl.y = incl.y - v[7].y;
    wexcl.z = incl.z - v[7].z;
    wexcl.w = incl.w - v[7].w;

    // warp total for this quad = inclusive value at rloc==3 (lane quad+24)
    float4 wsum = shfl_idx4(incl, (int)(quad + 24u));

    // ---- spine: 16 warps x 8 quads of float4 through smem ----
    if (rloc == 3u)
        wtot[w * 8u + quad] = wsum;
    __syncthreads();

    float4 off = wexcl;
    for (unsigned w2 = 0; w2 < w; ++w2) {
        float4 t = wtot[w2 * 8u + quad];
        off.x += t.x; off.y += t.y; off.z += t.z; off.w += t.w;
    }

    // ---- add offsets and store (same dense pattern as load) ----
#pragma unroll
    for (int j = 0; j < 8; ++j) {
        float4 o;
        o.x = v[j].x + off.x;
        o.y = v[j].y + off.y;
        o.z = v[j].z + off.z;
        o.w = v[j].w + off.w;
        out4[(size_t)(row0 + j) * (Wn / 4) + quad] = o;
    }
}

__global__ void __launch_bounds__(NTHREADS) fused_scan_kernel(const float* __restrict__ in,
                                                              float* __restrict__ out) {
    __shared__ float4 wtot[16 * 8];          // 2 KB spine

    const unsigned bid = blockIdx.x;
    const unsigned q = bid / 3u;
    if (bid == q * 3u) {
        do_scan_y(in, out, q, wtot);             // 2048 y-blocks
    } else {
        do_scan_x(in, out, bid - q - 1u);        // 4096 x-blocks
    }
}

extern "C" void kernel_launch(void* const* d_in, const int* in_sizes, int n_in,
                              void* d_out, int out_size) {
    const float* in = (const float*)d_in[0];
    float* out = (float*)d_out;
    fused_scan_kernel<<<GRID_BLOCKS, NTHREADS>>>(in, out);
}